// round 11
// baseline (speedup 1.0000x reference)
#include <cuda_runtime.h>

// EMA scan, FUSED single kernel: chunked decomposition + decaying look-back.
//   out[l,d,e] = a_e*x[l,d] + (1-a_e)*out[l-1,d,e],  out[-1,d,e] = x[0,d]
//
// CHUNK=32, oS_max = 0.9586^32 = 0.258; look-back J=8 -> trunc 2e-5 (<< 1e-3).
//
// Traffic argument: the 2-kernel version is pinned at the ~5.4TB/s LTS cap
// with 168MB total (x read twice). Fusing reads x ONCE: 148MB -> ~27.5us floor.
//
// Fused v2 fixes over the round-6 attempt:
//  * flags are MONOTONIC COUNTERS (no epoch-bump kernel, no reset): each block
//    reads its own flag's previous value at entry, target = old+1; publishes
//    target after fence. Graph replays are stream-serialized, so no block can
//    be a full run ahead -> race-free.
//  * phase A aggregates B straight from batched global loads while copying x
//    into smem (staging overlapped with compute, no pre-sync).
//  * pollers back off with __nanosleep.
//  * __launch_bounds__(256,8): 8 blocks/SM * 148 = 1184 slots >= 1024 blocks
//    -> all co-resident, spin-wait cannot deadlock.

#define LSEQ   8192
#define DFEAT  512
#define EMAS   8
#define CHUNK  32
#define NCHUNK (LSEQ / CHUNK)    // 256
#define DPB    128               // d's per block
#define NDG    (DFEAT / DPB)     // 4
#define TPB    (DPB * 2)         // 256 threads: 2 per d (4 states each)
#define LOOKB  8
#define NST    4                 // states per thread

__device__ float g_B[NCHUNK * DFEAT * EMAS];   // 4 MB scratch
__device__ int   g_flag[NCHUNK * NDG];         // zero-initialized counters

__global__ __launch_bounds__(TPB, 8)
void ema_fused(const float* __restrict__ x,
               const float* __restrict__ log_decay,
               float* __restrict__ out)
{
    __shared__ float xs[CHUNK][DPB];   // 16 KB
    __shared__ int   s_target;

    const int t  = threadIdx.x;
    const int dl = t >> 1;             // 0..127
    const int e0 = (t & 1) * NST;      // 0 or 4
    const int g  = blockIdx.y;
    const int d  = g * DPB + dl;
    const int k  = blockIdx.x;

    volatile int* flags = g_flag;

    if (t == 0) s_target = flags[k * NDG + g] + 1;   // this run's publish value

    float a[NST], o[NST];
    #pragma unroll
    for (int e = 0; e < NST; ++e) {
        float la = __ldg(log_decay + e0 + e);
        a[e] = 1.0f / (1.0f + expf(-la));
        o[e] = 1.0f - a[e];
    }

    // ---- phase A: aggregate B from global x, copying x into smem ----
    float c[NST];
    #pragma unroll
    for (int e = 0; e < NST; ++e) c[e] = 0.0f;

    const float* xp = x + (size_t)k * CHUNK * DFEAT + d;
    #pragma unroll
    for (int ii = 0; ii < CHUNK; ii += 4) {
        float xv[4];
        #pragma unroll
        for (int j = 0; j < 4; ++j)                    // front-batched MLP=4
            xv[j] = xp[(size_t)(ii + j) * DFEAT];
        if ((t & 1) == 0) {
            #pragma unroll
            for (int j = 0; j < 4; ++j)
                xs[ii + j][dl] = xv[j];
        }
        #pragma unroll
        for (int j = 0; j < 4; ++j)
            #pragma unroll
            for (int e = 0; e < NST; ++e)
                c[e] = fmaf(o[e], c[e], a[e] * xv[j]);
    }

    // publish B
    *reinterpret_cast<float4*>(g_B + ((size_t)k * DFEAT + d) * EMAS + e0) =
        make_float4(c[0], c[1], c[2], c[3]);
    __threadfence();
    __syncthreads();                       // B + xs + s_target all in place
    const int target = s_target;
    if (t == 0) flags[k * NDG + g] = target;

    // ---- wait for the LOOKB predecessors (same d-group) ----
    const int m = (k < LOOKB) ? k : LOOKB;
    if (t < m) {
        while (flags[(k - 1 - t) * NDG + g] < target) __nanosleep(64);
    }
    __syncthreads();
    __threadfence();                       // acquire side

    // ---- carry: Horner over last m aggregates (exact x0 seed if k<=J) ----
    float oS[NST];
    #pragma unroll
    for (int e = 0; e < NST; ++e) {
        float tmp = o[e];
        #pragma unroll
        for (int s = 0; s < 5; ++s) tmp *= tmp;        // o^32
        oS[e] = tmp;
    }

    const float x0 = (k <= LOOKB) ? __ldg(x + d) : 0.0f;
    #pragma unroll
    for (int e = 0; e < NST; ++e) c[e] = (k <= LOOKB) ? x0 : 0.0f;

    const float* bb = g_B + (size_t)d * EMAS + e0;
    const size_t CSTRIDE = (size_t)DFEAT * EMAS;
    for (int j = m; j >= 1; --j) {                     // oldest -> newest
        const float4 bv = *reinterpret_cast<const float4*>(
            bb + (size_t)(k - j) * CSTRIDE);
        c[0] = fmaf(oS[0], c[0], bv.x);
        c[1] = fmaf(oS[1], c[1], bv.y);
        c[2] = fmaf(oS[2], c[2], bv.z);
        c[3] = fmaf(oS[3], c[3], bv.w);
    }

    // ---- phase B: rescan from smem, streaming stores ----
    float* op = out + ((size_t)k * CHUNK * DFEAT + d) * EMAS + e0;
    #pragma unroll
    for (int i = 0; i < CHUNK; ++i) {
        const float xv = xs[i][dl];
        #pragma unroll
        for (int e = 0; e < NST; ++e)
            c[e] = fmaf(o[e], c[e], a[e] * xv);
        __stcs(reinterpret_cast<float4*>(op + (size_t)i * (DFEAT * EMAS)),
               make_float4(c[0], c[1], c[2], c[3]));
    }
}

extern "C" void kernel_launch(void* const* d_in, const int* in_sizes, int n_in,
                              void* d_out, int out_size)
{
    const float* x  = (const float*)d_in[0];
    const float* ld = (const float*)d_in[1];
    if (n_in >= 2 && in_sizes[0] == EMAS && in_sizes[1] == LSEQ * DFEAT) {
        x  = (const float*)d_in[1];
        ld = (const float*)d_in[0];
    }
    float* out = (float*)d_out;

    dim3 grid(NCHUNK, NDG);   // (256, 4) = 1024 blocks, all co-resident
    ema_fused<<<grid, TPB>>>(x, ld, out);
}